// round 15
// baseline (speedup 1.0000x reference)
#include <cuda_runtime.h>
#include <cuda_fp16.h>
#include <math.h>
#include <stdint.h>

#define NN 16384
#define EE 65536
#define GG 128
#define DD 64
#define FIN 64
#define EIN 16
#define HE 64
#define LL 3
#define NSTEPS 3
#define EPSV 1e-5f
#define NCHUNK 65              // 64 hidden k + 1 bias chunk
#define BSTRIDE 72             // padded fp16 row stride (conflict-free LDS)
#define BCH16 (64 * BSTRIDE)   // halfs per chunk image: 4608 (9216 B)

// ---------------- scratch (device globals; no allocation) ----------------
__device__ float d_x[NN * DD];
__device__ float d_agg[NN * DD];
__device__ float d_hT[NCHUNK * EE];  // edge hidden transposed + ones row (17 MB)
__device__ int   d_cnt[NN];
__device__ float d_invc[NN];
__device__ __align__(16) __half d_Bh[LL * NCHUNK * BCH16];  // fp16 B images

// ---------------- helpers ----------------
__device__ __forceinline__ uint32_t smem_u32(const void* p) {
    return (uint32_t)__cvta_generic_to_shared(p);
}
__device__ __forceinline__ uint32_t packh2(float a, float b) {  // lo=a, hi=b
    uint32_t r;
    asm("cvt.rn.f16x2.f32 %0, %1, %2;" : "=r"(r) : "f"(b), "f"(a));
    return r;
}
__device__ __forceinline__ void hmma(float* c, uint32_t a0, uint32_t a1, uint32_t a2,
                                     uint32_t a3, uint32_t b0, uint32_t b1) {
    asm volatile(
        "mma.sync.aligned.m16n8k16.row.col.f32.f16.f16.f32 "
        "{%0,%1,%2,%3}, {%4,%5,%6,%7}, {%8,%9}, {%0,%1,%2,%3};"
        : "+f"(c[0]), "+f"(c[1]), "+f"(c[2]), "+f"(c[3])
        : "r"(a0), "r"(a1), "r"(a2), "r"(a3), "r"(b0), "r"(b1));
}
#define CP_A16(s, g) asm volatile("cp.async.ca.shared.global [%0], [%1], 16;" :: "r"(s), "l"(g))
#define CP_A4(s, g)  asm volatile("cp.async.ca.shared.global [%0], [%1], 4;"  :: "r"(s), "l"(g))
#define CP_COMMIT()  asm volatile("cp.async.commit_group;")
#define CP_WAIT1()   asm volatile("cp.async.wait_group 1;")
#define CP_WAIT0()   asm volatile("cp.async.wait_group 0;")

// ---------------- small utility kernels ----------------
__global__ void k_zero0() {  // cnt + agg
    int i = blockIdx.x * blockDim.x + threadIdx.x;
    if (i < NN) d_cnt[i] = 0;
    if (i < NN * DD) d_agg[i] = 0.0f;
}
__global__ void k_count(const int* __restrict__ dst) {
    int i = blockIdx.x * blockDim.x + threadIdx.x;
    if (i < EE) atomicAdd(&d_cnt[dst[i]], 1);
}
__global__ void k_invc() {
    int i = blockIdx.x * blockDim.x + threadIdx.x;
    if (i < NN) d_invc[i] = 1.0f / (float)max(d_cnt[i], 1);
}
__global__ void k_ones() {  // hT row 64 = 1.0 (bias chunk)
    int i = blockIdx.x * blockDim.x + threadIdx.x;
    if (i < EE) d_hT[(size_t)64 * EE + i] = 1.0f;
}

// ---------------- prep: B chunk images (o-major rows, padded stride, fp16) --------
__global__ void k_prep_B(const float* __restrict__ mw2, const float* __restrict__ mb2) {
    int chunk = blockIdx.x;  // 0 .. LL*NCHUNK-1
    int l = chunk / NCHUNK, kc = chunk % NCHUNK;
    const float* sp = (kc < 64) ? (mw2 + ((size_t)l * 64 + kc) * (DD * DD))
                                : (mb2 + (size_t)l * (DD * DD));
    __half* hb = d_Bh + (size_t)chunk * BCH16;
    for (int i = threadIdx.x; i < DD * DD; i += 256) {
        int d = i >> 6, o = i & 63;  // sp[i] = M[kc][d][o]
        hb[o * BSTRIDE + d] = __float2half_rn(sp[i]);
    }
}

// ---------------- lin0: 64 nodes/block, one W load per block ----------------
__global__ __launch_bounds__(256) void k_lin0(const float* __restrict__ xin,
                                              const float* __restrict__ w,
                                              const float* __restrict__ b) {
    __shared__ float ws[FIN * DD];
    __shared__ float xs[64][FIN + 1];
    int t = threadIdx.x;
    int n0 = blockIdx.x * 64;
    for (int i = t; i < FIN * DD; i += 256) ws[i] = w[i];
    for (int i = t; i < 64 * FIN; i += 256) xs[i >> 6][i & 63] = xin[(size_t)n0 * FIN + i];
    __syncthreads();
    int g = t >> 6, o = t & 63;
    float bo = b[o];
#pragma unroll 4
    for (int n = g; n < 64; n += 4) {
        float acc = bo;
#pragma unroll
        for (int d = 0; d < FIN; d++) acc += xs[n][d] * ws[d * DD + o];
        d_x[(size_t)(n0 + n) * DD + o] = fmaxf(acc, 0.0f);
    }
}

// ---------------- edge hidden, transposed: hT[k][e] = relu(ea @ W1 + b1) ----------
__global__ __launch_bounds__(256) void k_edge_h(const float* __restrict__ ea,
                                                const float* __restrict__ w1,
                                                const float* __restrict__ b1) {
    __shared__ float ws[EIN * HE];
    __shared__ float bs[HE];
    int t = threadIdx.x;
    for (int i = t; i < EIN * HE; i += 256) ws[i] = w1[i];
    if (t < HE) bs[t] = b1[t];
    __syncthreads();
    int e = blockIdx.x * 128 + (t & 127);
    int k0 = (t >> 7) * 32;
    float ev[EIN];
    const float4* ep = (const float4*)(ea + (size_t)e * EIN);
#pragma unroll
    for (int i = 0; i < 4; i++) {
        float4 v = ep[i];
        ev[4 * i + 0] = v.x; ev[4 * i + 1] = v.y;
        ev[4 * i + 2] = v.z; ev[4 * i + 3] = v.w;
    }
    float acc[32];
#pragma unroll
    for (int kk = 0; kk < 32; kk++) acc[kk] = bs[k0 + kk];
#pragma unroll
    for (int j = 0; j < EIN; j++) {
        float evj = ev[j];
#pragma unroll
        for (int kk = 0; kk < 32; kk++) acc[kk] += evj * ws[j * HE + k0 + kk];
    }
#pragma unroll
    for (int kk = 0; kk < 32; kk++)
        d_hT[(size_t)(k0 + kk) * EE + e] = fmaxf(acc[kk], 0.0f);
}

// ---------------- edge message GEMM via warp MMA (single-pass fp16) ---------------
// Block: 128 edges, 4 warps. Warp tile: 32 edges x 64 outputs. (R11 verbatim)
__global__ __launch_bounds__(128) void k_edge_msg_hmma(const int* __restrict__ src,
                                                       const int* __restrict__ dst,
                                                       int layer) {
    __shared__ __half Bs[2][BCH16];  // 2 x 9216 B
    __shared__ float hs[2][128];

    int t = threadIdx.x, wid = t >> 5, lid = t & 31;
    int g = lid >> 2, tig = lid & 3;
    int e0 = blockIdx.x * 128;

    // ---- y fragments in registers (constant across chunks) ----
    float yv[4][16];
    int edge_id[4];
#pragma unroll
    for (int mt = 0; mt < 2; mt++)
#pragma unroll
        for (int rr = 0; rr < 2; rr++) {
            int e = e0 + wid * 32 + mt * 16 + g + rr * 8;
            edge_id[mt * 2 + rr] = e;
            const float* xr = d_x + (size_t)src[e] * DD;
#pragma unroll
            for (int w = 0; w < 4; w++) {
                float2 v0 = *(const float2*)(xr + w * 16 + tig * 2);
                float2 v1 = *(const float2*)(xr + w * 16 + 8 + tig * 2);
                yv[mt * 2 + rr][w * 4 + 0] = v0.x;
                yv[mt * 2 + rr][w * 4 + 1] = v0.y;
                yv[mt * 2 + rr][w * 4 + 2] = v1.x;
                yv[mt * 2 + rr][w * 4 + 3] = v1.y;
            }
        }

    float acc[2][8][4];
#pragma unroll
    for (int mt = 0; mt < 2; mt++)
#pragma unroll
        for (int nt = 0; nt < 8; nt++)
#pragma unroll
            for (int q = 0; q < 4; q++) acc[mt][nt][q] = 0.0f;

    const __half* Bh = d_Bh + (size_t)layer * NCHUNK * BCH16;

    uint32_t sB0 = smem_u32(&Bs[0][0]);
    uint32_t sB1 = smem_u32(&Bs[1][0]);
    uint32_t sh0 = smem_u32(&hs[0][0]);
    uint32_t sh1 = smem_u32(&hs[1][0]);

    auto issue_chunk = [&](int kc, int st) {
        const char* gB = (const char*)(Bh + (size_t)kc * BCH16);
        uint32_t sB = st ? sB1 : sB0;
        uint32_t sh = st ? sh1 : sh0;
#pragma unroll
        for (int q = 0; q < 4; q++)
            CP_A16(sB + (t + q * 128) * 16, gB + (size_t)(t + q * 128) * 16);
        if (t < 64) CP_A16(sB + (t + 512) * 16, gB + (size_t)(t + 512) * 16);
        CP_A4(sh + t * 4, (const char*)(d_hT + (size_t)kc * EE + e0 + t));
    };

    issue_chunk(0, 0);
    CP_COMMIT();

    for (int kc = 0; kc < NCHUNK; kc++) {
        int st = kc & 1;
        __syncthreads();
        if (kc + 1 < NCHUNK) {
            issue_chunk(kc + 1, st ^ 1);
            CP_COMMIT();
            CP_WAIT1();
        } else {
            CP_WAIT0();
        }
        __syncthreads();

        float h0  = hs[st][wid * 32 + g];
        float h0b = hs[st][wid * 32 + g + 8];
        float h1  = hs[st][wid * 32 + 16 + g];
        float h1b = hs[st][wid * 32 + 16 + g + 8];

#pragma unroll
        for (int w = 0; w < 4; w++) {
            uint32_t ah[2][4];
#pragma unroll
            for (int mt = 0; mt < 2; mt++) {
                float ha = mt ? h1 : h0;
                float hb = mt ? h1b : h0b;
                const float* y0 = yv[mt * 2 + 0];  // row g
                const float* y1 = yv[mt * 2 + 1];  // row g+8
                ah[mt][0] = packh2(ha * y0[w * 4 + 0], ha * y0[w * 4 + 1]);
                ah[mt][1] = packh2(hb * y1[w * 4 + 0], hb * y1[w * 4 + 1]);
                ah[mt][2] = packh2(ha * y0[w * 4 + 2], ha * y0[w * 4 + 3]);
                ah[mt][3] = packh2(hb * y1[w * 4 + 2], hb * y1[w * 4 + 3]);
            }
#pragma unroll
            for (int nt = 0; nt < 8; nt++) {
                int boff = (nt * 8 + g) * BSTRIDE + w * 16 + tig * 2;
                uint32_t b0 = *(const uint32_t*)(&Bs[st][0] + boff);
                uint32_t b1 = *(const uint32_t*)(&Bs[st][0] + boff + 8);
#pragma unroll
                for (int mt = 0; mt < 2; mt++)
                    hmma(acc[mt][nt], ah[mt][0], ah[mt][1], ah[mt][2], ah[mt][3], b0, b1);
            }
        }
    }

    // ---- scatter: agg[dst] += msg / deg ----
#pragma unroll
    for (int mt = 0; mt < 2; mt++)
#pragma unroll
        for (int rr = 0; rr < 2; rr++) {
            int e = edge_id[mt * 2 + rr];
            int dn = dst[e];
            float ic = d_invc[dn];
            float* p = d_agg + (size_t)dn * DD + tig * 2;
#pragma unroll
            for (int nt = 0; nt < 8; nt++) {
                atomicAdd(&p[nt * 8 + 0], acc[mt][nt][rr * 2 + 0] * ic);
                atomicAdd(&p[nt * 8 + 1], acc[mt][nt][rr * 2 + 1] * ic);
            }
        }
}

// ---------------- root: 64 nodes/block, one W load per block ----------------
__global__ __launch_bounds__(256) void k_root(const float* __restrict__ w,
                                              const float* __restrict__ b) {
    __shared__ float ws[DD * DD];
    __shared__ float xs[64][DD + 1];
    int t = threadIdx.x;
    int n0 = blockIdx.x * 64;
    for (int i = t; i < DD * DD; i += 256) ws[i] = w[i];
    for (int i = t; i < 64 * DD; i += 256) xs[i >> 6][i & 63] = d_x[(size_t)n0 * DD + i];
    __syncthreads();
    int g = t >> 6, o = t & 63;
    float bo = b[o];
#pragma unroll 4
    for (int n = g; n < 64; n += 4) {
        size_t idx = (size_t)(n0 + n) * DD + o;
        float acc = bo + d_agg[idx];
#pragma unroll
        for (int d = 0; d < DD; d++) acc += xs[n][d] * ws[d * DD + o];
        d_agg[idx] = fmaxf(acc, 0.0f);
    }
}

// ---------------- GraphNorm + residual; 4-way reductions; zeroes agg --------------
__global__ __launch_bounds__(256) void k_gnorm(const float* __restrict__ gw,
                                               const float* __restrict__ gb,
                                               const float* __restrict__ gs) {
    __shared__ float s[128][DD + 1];
    __shared__ float part[4][DD];
    __shared__ float mean[DD];
    __shared__ float var[DD];
    int g = blockIdx.x, t = threadIdx.x;
    int q = t >> 6, d = t & 63;
    const float* xc = d_agg + (size_t)g * 128 * DD;
    for (int i = t; i < 128 * DD; i += 256) s[i >> 6][i & 63] = xc[i];
    __syncthreads();
    {
        float m = 0.0f;
#pragma unroll
        for (int n = 0; n < 32; n++) m += s[q * 32 + n][d];
        part[q][d] = m;
    }
    __syncthreads();
    if (t < DD) mean[t] = (part[0][t] + part[1][t] + part[2][t] + part[3][t]) * (1.0f / 128.0f);
    __syncthreads();
    {
        float gsd = gs[d] * mean[d];
        float v = 0.0f;
#pragma unroll
        for (int n = 0; n < 32; n++) {
            float sv = s[q * 32 + n][d] - gsd;
            s[q * 32 + n][d] = sv;
            v += sv * sv;
        }
        part[q][d] = v;
    }
    __syncthreads();
    if (t < DD) var[t] = (part[0][t] + part[1][t] + part[2][t] + part[3][t]) * (1.0f / 128.0f);
    __syncthreads();
    {
        float wv = gw[d] * rsqrtf(var[d] + EPSV);
        float bv = gb[d];
#pragma unroll
        for (int n = 0; n < 32; n++) {
            size_t gi = (size_t)g * 128 * DD + (q * 32 + n) * DD + d;
            d_x[gi] = wv * s[q * 32 + n][d] + bv + d_x[gi];
            d_agg[gi] = 0.0f;  // ready for next layer's scatter
        }
    }
}

// ---------------- Set2Set (3 steps) + head, one block per graph ----------------
__global__ __launch_bounds__(128) void k_s2s(const float* __restrict__ wih,
                                             const float* __restrict__ whh,
                                             const float* __restrict__ bih,
                                             const float* __restrict__ bhh,
                                             const float* __restrict__ hw1,
                                             const float* __restrict__ hb1,
                                             const float* __restrict__ hw2,
                                             const float* __restrict__ hb2,
                                             float* __restrict__ out) {
    __shared__ float sx[128][DD + 1];
    __shared__ float q_star[2 * DD];
    __shared__ float sh[DD], sc[DD];
    __shared__ float gates[4 * DD];
    __shared__ float red[128];
    __shared__ float sa[128];
    __shared__ float sr[DD];
    int g = blockIdx.x, t = threadIdx.x;
    const float* xg = d_x + (size_t)g * 128 * DD;
    for (int i = t; i < 128 * DD; i += 128) sx[i >> 6][i & 63] = xg[i];
    q_star[t] = 0.0f;
    if (t < DD) { sh[t] = 0.0f; sc[t] = 0.0f; }
    __syncthreads();

    for (int step = 0; step < NSTEPS; step++) {
#pragma unroll
        for (int rr = 0; rr < 2; rr++) {
            int r = t + rr * 128;
            float acc = bih[r] + bhh[r];
            const float* wr = wih + (size_t)r * (2 * DD);
            for (int j = 0; j < 2 * DD; j++) acc += q_star[j] * wr[j];
            const float* vr = whh + (size_t)r * DD;
            for (int j = 0; j < DD; j++) acc += sh[j] * vr[j];
            gates[r] = acc;
        }
        __syncthreads();
        if (t < DD) {
            float ig = 1.0f / (1.0f + expf(-gates[t]));
            float fg = 1.0f / (1.0f + expf(-gates[DD + t]));
            float gg = tanhf(gates[2 * DD + t]);
            float og = 1.0f / (1.0f + expf(-gates[3 * DD + t]));
            float c = fg * sc[t] + ig * gg;
            sc[t] = c;
            sh[t] = og * tanhf(c);
        }
        __syncthreads();
        float ee = 0.0f;
#pragma unroll
        for (int d = 0; d < DD; d++) ee += sx[t][d] * sh[d];
        red[t] = ee;
        __syncthreads();
        for (int off = 64; off; off >>= 1) {
            if (t < off) red[t] = fmaxf(red[t], red[t + off]);
            __syncthreads();
        }
        float emax = red[0];
        __syncthreads();
        float ex = expf(ee - emax);
        red[t] = ex;
        __syncthreads();
        for (int off = 64; off; off >>= 1) {
            if (t < off) red[t] += red[t + off];
            __syncthreads();
        }
        float denom = red[0];
        sa[t] = ex / denom;
        __syncthreads();
        if (t < DD) {
            float r = 0.0f;
            for (int n = 0; n < 128; n++) r += sa[n] * sx[n][t];
            sr[t] = r;
        }
        __syncthreads();
        q_star[t] = (t < DD) ? sh[t] : sr[t - DD];
        __syncthreads();
    }
    if (t < DD) {
        float acc = hb1[t];
        for (int j = 0; j < 2 * DD; j++) acc += q_star[j] * hw1[j * DD + t];
        red[t] = fmaxf(acc, 0.0f) * hw2[t];
    }
    __syncthreads();
    if (t < 32) {
        float v = red[t] + red[t + 32];
        for (int off = 16; off; off >>= 1) v += __shfl_down_sync(0xffffffffu, v, off);
        if (t == 0) out[g] = v + hb2[0];
    }
}

// ---------------- launch ----------------
extern "C" void kernel_launch(void* const* d_in, const int* in_sizes, int n_in,
                              void* d_out, int out_size) {
    const float* x     = (const float*)d_in[0];
    const int*   ei    = (const int*)d_in[1];
    const float* ea    = (const float*)d_in[2];
    const float* lin0w = (const float*)d_in[4];
    const float* lin0b = (const float*)d_in[5];
    const float* mw1   = (const float*)d_in[6];
    const float* mb1   = (const float*)d_in[7];
    const float* mw2   = (const float*)d_in[8];
    const float* mb2   = (const float*)d_in[9];
    const float* rootw = (const float*)d_in[10];
    const float* convb = (const float*)d_in[11];
    const float* gnw   = (const float*)d_in[12];
    const float* gnb   = (const float*)d_in[13];
    const float* gns   = (const float*)d_in[14];
    const float* wih   = (const float*)d_in[15];
    const float* whh   = (const float*)d_in[16];
    const float* bih   = (const float*)d_in[17];
    const float* bhh   = (const float*)d_in[18];
    const float* hw1   = (const float*)d_in[19];
    const float* hb1   = (const float*)d_in[20];
    const float* hw2   = (const float*)d_in[21];
    const float* hb2   = (const float*)d_in[22];
    float* out = (float*)d_out;

    const int* src = ei;
    const int* dst = ei + EE;

    k_zero0<<<(NN * DD) / 256, 256>>>();
    k_count<<<EE / 256, 256>>>(dst);
    k_invc<<<NN / 256, 256>>>();
    k_lin0<<<NN / 64, 256>>>(x, lin0w, lin0b);
    k_prep_B<<<LL * NCHUNK, 256>>>(mw2, mb2);
    k_ones<<<EE / 256, 256>>>();

    for (int l = 0; l < LL; l++) {
        k_edge_h<<<EE / 128, 256>>>(ea, mw1 + (size_t)l * EIN * HE, mb1 + (size_t)l * HE);
        k_edge_msg_hmma<<<EE / 128, 128>>>(src, dst, l);
        k_root<<<NN / 64, 256>>>(rootw + (size_t)l * DD * DD, convb + (size_t)l * DD);
        k_gnorm<<<GG, 256>>>(gnw + (size_t)l * DD, gnb + (size_t)l * DD, gns + (size_t)l * DD);
    }

    k_s2s<<<GG, 128>>>(wih, whh, bih, bhh, hw1, hb1, hw2, hb2, out);
}

// round 16
// speedup vs baseline: 1.0315x; 1.0315x over previous
#include <cuda_runtime.h>
#include <cuda_fp16.h>
#include <math.h>
#include <stdint.h>

#define NN 16384
#define EE 65536
#define GG 128
#define DD 64
#define FIN 64
#define EIN 16
#define HE 64
#define LL 3
#define NSTEPS 3
#define EPSV 1e-5f
#define NCHUNK 65              // 64 hidden k + 1 bias chunk
#define BSTRIDE 72             // padded fp16 row stride (conflict-free LDS)
#define BCH16 (64 * BSTRIDE)   // halfs per chunk image: 4608 (9216 B)

// ---------------- scratch (device globals; no allocation) ----------------
__device__ float d_x[NN * DD];
__device__ float d_agg[NN * DD];
__device__ __half d_hT[NCHUNK * EE];  // edge hidden transposed + ones row (fp16, 8.5 MB)
__device__ int   d_cnt[NN];
__device__ float d_invc[NN];
__device__ __align__(16) __half d_Bh[LL * NCHUNK * BCH16];  // fp16 B images

// ---------------- helpers ----------------
__device__ __forceinline__ uint32_t smem_u32(const void* p) {
    return (uint32_t)__cvta_generic_to_shared(p);
}
__device__ __forceinline__ uint32_t packh2(float a, float b) {  // lo=a, hi=b
    uint32_t r;
    asm("cvt.rn.f16x2.f32 %0, %1, %2;" : "=r"(r) : "f"(b), "f"(a));
    return r;
}
__device__ __forceinline__ void hmma(float* c, uint32_t a0, uint32_t a1, uint32_t a2,
                                     uint32_t a3, uint32_t b0, uint32_t b1) {
    asm volatile(
        "mma.sync.aligned.m16n8k16.row.col.f32.f16.f16.f32 "
        "{%0,%1,%2,%3}, {%4,%5,%6,%7}, {%8,%9}, {%0,%1,%2,%3};"
        : "+f"(c[0]), "+f"(c[1]), "+f"(c[2]), "+f"(c[3])
        : "r"(a0), "r"(a1), "r"(a2), "r"(a3), "r"(b0), "r"(b1));
}
#define CP_A16(s, g) asm volatile("cp.async.ca.shared.global [%0], [%1], 16;" :: "r"(s), "l"(g))
#define CP_A4(s, g)  asm volatile("cp.async.ca.shared.global [%0], [%1], 4;"  :: "r"(s), "l"(g))
#define CP_COMMIT()  asm volatile("cp.async.commit_group;")
#define CP_WAIT1()   asm volatile("cp.async.wait_group 1;")
#define CP_WAIT0()   asm volatile("cp.async.wait_group 0;")

// ---------------- [0] zero cnt + agg (single pass) ----------------
__global__ void k_zero0() {
    int i = blockIdx.x * blockDim.x + threadIdx.x;
    if (i < NN) d_cnt[i] = 0;
    if (i < NN * DD) d_agg[i] = 0.0f;
}
__global__ void k_count(const int* __restrict__ dst) {
    int i = blockIdx.x * blockDim.x + threadIdx.x;
    if (i < EE) atomicAdd(&d_cnt[dst[i]], 1);
}
__global__ void k_invc() {
    int i = blockIdx.x * blockDim.x + threadIdx.x;
    if (i < NN) d_invc[i] = 1.0f / (float)max(d_cnt[i], 1);
}
__global__ void k_ones() {  // hT row 64 = 1.0 (bias chunk)
    int i = blockIdx.x * blockDim.x + threadIdx.x;
    if (i < EE) d_hT[(size_t)64 * EE + i] = __float2half_rn(1.0f);
}

// ---------------- prep: B chunk images (o-major rows, padded stride, fp16) --------
__global__ void k_prep_B(const float* __restrict__ mw2, const float* __restrict__ mb2) {
    int chunk = blockIdx.x;  // 0 .. LL*NCHUNK-1
    int l = chunk / NCHUNK, kc = chunk % NCHUNK;
    const float* sp = (kc < 64) ? (mw2 + ((size_t)l * 64 + kc) * (DD * DD))
                                : (mb2 + (size_t)l * (DD * DD));
    __half* hb = d_Bh + (size_t)chunk * BCH16;
    for (int i = threadIdx.x; i < DD * DD; i += 256) {
        int d = i >> 6, o = i & 63;  // sp[i] = M[kc][d][o]
        hb[o * BSTRIDE + d] = __float2half_rn(sp[i]);
    }
}

// ---------------- lin0: x = relu(x_in @ W + b)  (R11 4-node/block shape) ----------
__global__ __launch_bounds__(256) void k_lin0(const float* __restrict__ xin,
                                              const float* __restrict__ w,
                                              const float* __restrict__ b) {
    __shared__ float ws[FIN * DD];
    __shared__ float xs[4][FIN];
    int t = threadIdx.x;
    for (int i = t; i < FIN * DD; i += 256) ws[i] = w[i];
    int n0 = blockIdx.x * 4;
    {
        int li = t >> 6, d = t & 63;
        xs[li][d] = xin[(size_t)(n0 + li) * FIN + d];
    }
    __syncthreads();
    int li = t >> 6, o = t & 63;
    float acc = b[o];
#pragma unroll
    for (int d = 0; d < FIN; d++) acc += xs[li][d] * ws[d * DD + o];
    d_x[(size_t)(n0 + li) * DD + o] = fmaxf(acc, 0.0f);
}

// ---------------- edge hidden, transposed fp16: hT[k][e] = relu(ea @ W1 + b1) -----
__global__ __launch_bounds__(256) void k_edge_h(const float* __restrict__ ea,
                                                const float* __restrict__ w1,
                                                const float* __restrict__ b1) {
    __shared__ float ws[EIN * HE];
    __shared__ float bs[HE];
    int t = threadIdx.x;
    for (int i = t; i < EIN * HE; i += 256) ws[i] = w1[i];
    if (t < HE) bs[t] = b1[t];
    __syncthreads();
    int e = blockIdx.x * 128 + (t & 127);
    int k0 = (t >> 7) * 32;
    float ev[EIN];
    const float4* ep = (const float4*)(ea + (size_t)e * EIN);
#pragma unroll
    for (int i = 0; i < 4; i++) {
        float4 v = ep[i];
        ev[4 * i + 0] = v.x; ev[4 * i + 1] = v.y;
        ev[4 * i + 2] = v.z; ev[4 * i + 3] = v.w;
    }
    float acc[32];
#pragma unroll
    for (int kk = 0; kk < 32; kk++) acc[kk] = bs[k0 + kk];
#pragma unroll
    for (int j = 0; j < EIN; j++) {
        float evj = ev[j];
#pragma unroll
        for (int kk = 0; kk < 32; kk++) acc[kk] += evj * ws[j * HE + k0 + kk];
    }
#pragma unroll
    for (int kk = 0; kk < 32; kk++)
        d_hT[(size_t)(k0 + kk) * EE + e] = __float2half_rn(fmaxf(acc[kk], 0.0f));
}

// ---------------- edge message GEMM via warp MMA (single-pass fp16) ---------------
// Block: 128 edges, 4 warps. Warp tile: 32 edges x 64 outputs. (R11 compute verbatim;
// h staging now fp16: cp.async 4B per 2 edges)
__global__ __launch_bounds__(128) void k_edge_msg_hmma(const int* __restrict__ src,
                                                       const int* __restrict__ dst,
                                                       int layer) {
    __shared__ __half Bs[2][BCH16];  // 2 x 9216 B
    __shared__ __half hs[2][128];

    int t = threadIdx.x, wid = t >> 5, lid = t & 31;
    int g = lid >> 2, tig = lid & 3;
    int e0 = blockIdx.x * 128;

    // ---- y fragments in registers (constant across chunks) ----
    float yv[4][16];
    int edge_id[4];
#pragma unroll
    for (int mt = 0; mt < 2; mt++)
#pragma unroll
        for (int rr = 0; rr < 2; rr++) {
            int e = e0 + wid * 32 + mt * 16 + g + rr * 8;
            edge_id[mt * 2 + rr] = e;
            const float* xr = d_x + (size_t)src[e] * DD;
#pragma unroll
            for (int w = 0; w < 4; w++) {
                float2 v0 = *(const float2*)(xr + w * 16 + tig * 2);
                float2 v1 = *(const float2*)(xr + w * 16 + 8 + tig * 2);
                yv[mt * 2 + rr][w * 4 + 0] = v0.x;
                yv[mt * 2 + rr][w * 4 + 1] = v0.y;
                yv[mt * 2 + rr][w * 4 + 2] = v1.x;
                yv[mt * 2 + rr][w * 4 + 3] = v1.y;
            }
        }

    float acc[2][8][4];
#pragma unroll
    for (int mt = 0; mt < 2; mt++)
#pragma unroll
        for (int nt = 0; nt < 8; nt++)
#pragma unroll
            for (int q = 0; q < 4; q++) acc[mt][nt][q] = 0.0f;

    const __half* Bh = d_Bh + (size_t)layer * NCHUNK * BCH16;

    uint32_t sB0 = smem_u32(&Bs[0][0]);
    uint32_t sB1 = smem_u32(&Bs[1][0]);
    uint32_t sh0 = smem_u32(&hs[0][0]);
    uint32_t sh1 = smem_u32(&hs[1][0]);

    auto issue_chunk = [&](int kc, int st) {
        const char* gB = (const char*)(Bh + (size_t)kc * BCH16);
        uint32_t sB = st ? sB1 : sB0;
        uint32_t sh = st ? sh1 : sh0;
#pragma unroll
        for (int q = 0; q < 4; q++)
            CP_A16(sB + (t + q * 128) * 16, gB + (size_t)(t + q * 128) * 16);
        if (t < 64) {
            CP_A16(sB + (t + 512) * 16, gB + (size_t)(t + 512) * 16);
            // h: 128 halves = 256 B, 4B per thread for t<64
            CP_A4(sh + t * 4, (const char*)(d_hT + (size_t)kc * EE + e0 + 2 * t));
        }
    };

    issue_chunk(0, 0);
    CP_COMMIT();

    for (int kc = 0; kc < NCHUNK; kc++) {
        int st = kc & 1;
        __syncthreads();
        if (kc + 1 < NCHUNK) {
            issue_chunk(kc + 1, st ^ 1);
            CP_COMMIT();
            CP_WAIT1();
        } else {
            CP_WAIT0();
        }
        __syncthreads();

        float h0  = __half2float(hs[st][wid * 32 + g]);
        float h0b = __half2float(hs[st][wid * 32 + g + 8]);
        float h1  = __half2float(hs[st][wid * 32 + 16 + g]);
        float h1b = __half2float(hs[st][wid * 32 + 16 + g + 8]);

#pragma unroll
        for (int w = 0; w < 4; w++) {
            uint32_t ah[2][4];
#pragma unroll
            for (int mt = 0; mt < 2; mt++) {
                float ha = mt ? h1 : h0;
                float hb = mt ? h1b : h0b;
                const float* y0 = yv[mt * 2 + 0];  // row g
                const float* y1 = yv[mt * 2 + 1];  // row g+8
                ah[mt][0] = packh2(ha * y0[w * 4 + 0], ha * y0[w * 4 + 1]);
                ah[mt][1] = packh2(hb * y1[w * 4 + 0], hb * y1[w * 4 + 1]);
                ah[mt][2] = packh2(ha * y0[w * 4 + 2], ha * y0[w * 4 + 3]);
                ah[mt][3] = packh2(hb * y1[w * 4 + 2], hb * y1[w * 4 + 3]);
            }
#pragma unroll
            for (int nt = 0; nt < 8; nt++) {
                int boff = (nt * 8 + g) * BSTRIDE + w * 16 + tig * 2;
                uint32_t b0 = *(const uint32_t*)(&Bs[st][0] + boff);
                uint32_t b1 = *(const uint32_t*)(&Bs[st][0] + boff + 8);
#pragma unroll
                for (int mt = 0; mt < 2; mt++)
                    hmma(acc[mt][nt], ah[mt][0], ah[mt][1], ah[mt][2], ah[mt][3], b0, b1);
            }
        }
    }

    // ---- scatter: agg[dst] += msg / deg ----
#pragma unroll
    for (int mt = 0; mt < 2; mt++)
#pragma unroll
        for (int rr = 0; rr < 2; rr++) {
            int e = edge_id[mt * 2 + rr];
            int dn = dst[e];
            float ic = d_invc[dn];
            float* p = d_agg + (size_t)dn * DD + tig * 2;
#pragma unroll
            for (int nt = 0; nt < 8; nt++) {
                atomicAdd(&p[nt * 8 + 0], acc[mt][nt][rr * 2 + 0] * ic);
                atomicAdd(&p[nt * 8 + 1], acc[mt][nt][rr * 2 + 1] * ic);
            }
        }
}

// ---------------- root: xc = relu(agg + x @ root_w + b)  (R11 shape) --------------
__global__ __launch_bounds__(256) void k_root(const float* __restrict__ w,
                                              const float* __restrict__ b) {
    __shared__ float ws[DD * DD];
    __shared__ float xs[4][DD];
    int t = threadIdx.x;
    for (int i = t; i < DD * DD; i += 256) ws[i] = w[i];
    int n0 = blockIdx.x * 4;
    {
        int li = t >> 6, d = t & 63;
        xs[li][d] = d_x[(size_t)(n0 + li) * DD + d];
    }
    __syncthreads();
    int li = t >> 6, o = t & 63;
    size_t idx = (size_t)(n0 + li) * DD + o;
    float acc = b[o] + d_agg[idx];
#pragma unroll
    for (int d = 0; d < DD; d++) acc += xs[li][d] * ws[d * DD + o];
    d_agg[idx] = fmaxf(acc, 0.0f);
}

// ---------------- GraphNorm + residual; zeroes agg for next layer ----------------
__global__ __launch_bounds__(256) void k_gnorm(const float* __restrict__ gw,
                                               const float* __restrict__ gb,
                                               const float* __restrict__ gs) {
    __shared__ float s[128][DD + 1];
    __shared__ float mean[DD];
    __shared__ float var[DD];
    int g = blockIdx.x, t = threadIdx.x;
    const float* xc = d_agg + (size_t)g * 128 * DD;
    for (int i = t; i < 128 * DD; i += 256) s[i >> 6][i & 63] = xc[i];
    __syncthreads();
    if (t < DD) {
        float m = 0.0f;
        for (int n = 0; n < 128; n++) m += s[n][t];
        mean[t] = m * (1.0f / 128.0f);
    }
    __syncthreads();
    for (int i = t; i < 128 * DD; i += 256) {
        int n = i >> 6, d = i & 63;
        s[n][d] -= gs[d] * mean[d];
    }
    __syncthreads();
    if (t < DD) {
        float v = 0.0f;
        for (int n = 0; n < 128; n++) v += s[n][t] * s[n][t];
        var[t] = v * (1.0f / 128.0f);
    }
    __syncthreads();
    for (int i = t; i < 128 * DD; i += 256) {
        int n = i >> 6, d = i & 63;
        float xn = gw[d] * s[n][d] * rsqrtf(var[d] + EPSV) + gb[d];
        size_t gi = (size_t)g * 128 * DD + i;
        d_x[gi] = xn + d_x[gi];
        d_agg[gi] = 0.0f;  // ready for next layer's scatter
    }
}

// ---------------- Set2Set (3 steps) + head, one block per graph ----------------
__global__ __launch_bounds__(128) void k_s2s(const float* __restrict__ wih,
                                             const float* __restrict__ whh,
                                             const float* __restrict__ bih,
                                             const float* __restrict__ bhh,
                                             const float* __restrict__ hw1,
                                             const float* __restrict__ hb1,
                                             const float* __restrict__ hw2,
                                             const float* __restrict__ hb2,
                                             float* __restrict__ out) {
    __shared__ float sx[128][DD + 1];
    __shared__ float q_star[2 * DD];
    __shared__ float sh[DD], sc[DD];
    __shared__ float gates[4 * DD];
    __shared__ float red[128];
    __shared__ float sa[128];
    __shared__ float sr[DD];
    int g = blockIdx.x, t = threadIdx.x;
    const float* xg = d_x + (size_t)g * 128 * DD;
    for (int i = t; i < 128 * DD; i += 128) sx[i >> 6][i & 63] = xg[i];
    q_star[t] = 0.0f;
    if (t < DD) { sh[t] = 0.0f; sc[t] = 0.0f; }
    __syncthreads();

    for (int step = 0; step < NSTEPS; step++) {
#pragma unroll
        for (int rr = 0; rr < 2; rr++) {
            int r = t + rr * 128;
            float acc = bih[r] + bhh[r];
            const float* wr = wih + (size_t)r * (2 * DD);
            for (int j = 0; j < 2 * DD; j++) acc += q_star[j] * wr[j];
            const float* vr = whh + (size_t)r * DD;
            for (int j = 0; j < DD; j++) acc += sh[j] * vr[j];
            gates[r] = acc;
        }
        __syncthreads();
        if (t < DD) {
            float ig = 1.0f / (1.0f + expf(-gates[t]));
            float fg = 1.0f / (1.0f + expf(-gates[DD + t]));
            float gg = tanhf(gates[2 * DD + t]);
            float og = 1.0f / (1.0f + expf(-gates[3 * DD + t]));
            float c = fg * sc[t] + ig * gg;
            sc[t] = c;
            sh[t] = og * tanhf(c);
        }
        __syncthreads();
        float ee = 0.0f;
#pragma unroll
        for (int d = 0; d < DD; d++) ee += sx[t][d] * sh[d];
        red[t] = ee;
        __syncthreads();
        for (int off = 64; off; off >>= 1) {
            if (t < off) red[t] = fmaxf(red[t], red[t + off]);
            __syncthreads();
        }
        float emax = red[0];
        __syncthreads();
        float ex = expf(ee - emax);
        red[t] = ex;
        __syncthreads();
        for (int off = 64; off; off >>= 1) {
            if (t < off) red[t] += red[t + off];
            __syncthreads();
        }
        float denom = red[0];
        sa[t] = ex / denom;
        __syncthreads();
        if (t < DD) {
            float r = 0.0f;
            for (int n = 0; n < 128; n++) r += sa[n] * sx[n][t];
            sr[t] = r;
        }
        __syncthreads();
        q_star[t] = (t < DD) ? sh[t] : sr[t - DD];
        __syncthreads();
    }
    if (t < DD) {
        float acc = hb1[t];
        for (int j = 0; j < 2 * DD; j++) acc += q_star[j] * hw1[j * DD + t];
        red[t] = fmaxf(acc, 0.0f) * hw2[t];
    }
    __syncthreads();
    if (t < 32) {
        float v = red[t] + red[t + 32];
        for (int off = 16; off; off >>= 1) v += __shfl_down_sync(0xffffffffu, v, off);
        if (t == 0) out[g] = v + hb2[0];
    }
}

// ---------------- launch ----------------
extern "C" void kernel_launch(void* const* d_in, const int* in_sizes, int n_in,
                              void* d_out, int out_size) {
    const float* x     = (const float*)d_in[0];
    const int*   ei    = (const int*)d_in[1];
    const float* ea    = (const float*)d_in[2];
    const float* lin0w = (const float*)d_in[4];
    const float* lin0b = (const float*)d_in[5];
    const float* mw1   = (const float*)d_in[6];
    const float* mb1   = (const float*)d_in[7];
    const float* mw2   = (const float*)d_in[8];
    const float* mb2   = (const float*)d_in[9];
    const float* rootw = (const float*)d_in[10];
    const float* convb = (const float*)d_in[11];
    const float* gnw   = (const float*)d_in[12];
    const float* gnb   = (const float*)d_in[13];
    const float* gns   = (const float*)d_in[14];
    const float* wih   = (const float*)d_in[15];
    const float* whh   = (const float*)d_in[16];
    const float* bih   = (const float*)d_in[17];
    const float* bhh   = (const float*)d_in[18];
    const float* hw1   = (const float*)d_in[19];
    const float* hb1   = (const float*)d_in[20];
    const float* hw2   = (const float*)d_in[21];
    const float* hb2   = (const float*)d_in[22];
    float* out = (float*)d_out;

    const int* src = ei;
    const int* dst = ei + EE;

    k_zero0<<<(NN * DD) / 256, 256>>>();
    k_count<<<EE / 256, 256>>>(dst);
    k_invc<<<NN / 256, 256>>>();
    k_lin0<<<NN / 4, 256>>>(x, lin0w, lin0b);
    k_prep_B<<<LL * NCHUNK, 256>>>(mw2, mb2);
    k_ones<<<EE / 256, 256>>>();

    for (int l = 0; l < LL; l++) {
        k_edge_h<<<EE / 128, 256>>>(ea, mw1 + (size_t)l * EIN * HE, mb1 + (size_t)l * HE);
        k_edge_msg_hmma<<<EE / 128, 128>>>(src, dst, l);
        k_root<<<NN / 4, 256>>>(rootw + (size_t)l * DD * DD, convb + (size_t)l * DD);
        k_gnorm<<<GG, 256>>>(gnw + (size_t)l * DD, gnb + (size_t)l * DD, gns + (size_t)l * DD);
    }

    k_s2s<<<GG, 128>>>(wih, whh, bih, bhh, hw1, hb1, hw2, hb2, out);
}

// round 17
// speedup vs baseline: 1.1091x; 1.0753x over previous
#include <cuda_runtime.h>
#include <cuda_fp16.h>
#include <math.h>
#include <stdint.h>

#define NN 16384
#define EE 65536
#define GG 128
#define DD 64
#define FIN 64
#define EIN 16
#define HE 64
#define LL 3
#define NSTEPS 3
#define EPSV 1e-5f
#define NCHUNK 65              // 64 hidden k + 1 bias chunk
#define BSTRIDE 72             // padded fp16 row stride (conflict-free LDS)
#define BCH16 (64 * BSTRIDE)   // halfs per chunk image: 4608 (9216 B)

// ---------------- scratch (device globals; no allocation) ----------------
__device__ float d_x[NN * DD];
__device__ float d_agg[NN * DD];
__device__ float d_hT[LL * NCHUNK * EE];  // per-layer hT slabs + ones rows (51 MB)
__device__ int   d_cnt[NN];
__device__ float d_invc[NN];
__device__ __align__(16) __half d_Bh[LL * NCHUNK * BCH16];  // fp16 B images

// ---------------- helpers ----------------
__device__ __forceinline__ uint32_t smem_u32(const void* p) {
    return (uint32_t)__cvta_generic_to_shared(p);
}
__device__ __forceinline__ uint32_t packh2(float a, float b) {  // lo=a, hi=b
    uint32_t r;
    asm("cvt.rn.f16x2.f32 %0, %1, %2;" : "=r"(r) : "f"(b), "f"(a));
    return r;
}
__device__ __forceinline__ void hmma(float* c, uint32_t a0, uint32_t a1, uint32_t a2,
                                     uint32_t a3, uint32_t b0, uint32_t b1) {
    asm volatile(
        "mma.sync.aligned.m16n8k16.row.col.f32.f16.f16.f32 "
        "{%0,%1,%2,%3}, {%4,%5,%6,%7}, {%8,%9}, {%0,%1,%2,%3};"
        : "+f"(c[0]), "+f"(c[1]), "+f"(c[2]), "+f"(c[3])
        : "r"(a0), "r"(a1), "r"(a2), "r"(a3), "r"(b0), "r"(b1));
}
#define CP_A16(s, g) asm volatile("cp.async.ca.shared.global [%0], [%1], 16;" :: "r"(s), "l"(g))
#define CP_A4(s, g)  asm volatile("cp.async.ca.shared.global [%0], [%1], 4;"  :: "r"(s), "l"(g))
#define CP_COMMIT()  asm volatile("cp.async.commit_group;")
#define CP_WAIT1()   asm volatile("cp.async.wait_group 1;")
#define CP_WAIT0()   asm volatile("cp.async.wait_group 0;")

// ---------------- [0] zero cnt + agg ----------------
__global__ void k_zero0() {
    int i = blockIdx.x * blockDim.x + threadIdx.x;
    if (i < NN) d_cnt[i] = 0;
    if (i < NN * DD) d_agg[i] = 0.0f;
}
// ---------------- [1] degree count ----------------
__global__ void k_count(const int* __restrict__ dst) {
    int i = blockIdx.x * blockDim.x + threadIdx.x;
    if (i < EE) atomicAdd(&d_cnt[dst[i]], 1);
}

// ---------------- [2] lin0 (R11 shape) + invc fold ----------------
__global__ __launch_bounds__(256) void k_lin0(const float* __restrict__ xin,
                                              const float* __restrict__ w,
                                              const float* __restrict__ b) {
    __shared__ float ws[FIN * DD];
    __shared__ float xs[4][FIN];
    int t = threadIdx.x;
    if (blockIdx.x < NN / 256) {  // invc fold (count completed in prior launch)
        int i = blockIdx.x * 256 + t;
        d_invc[i] = 1.0f / (float)max(d_cnt[i], 1);
    }
    for (int i = t; i < FIN * DD; i += 256) ws[i] = w[i];
    int n0 = blockIdx.x * 4;
    {
        int li = t >> 6, d = t & 63;
        xs[li][d] = xin[(size_t)(n0 + li) * FIN + d];
    }
    __syncthreads();
    int li = t >> 6, o = t & 63;
    float acc = b[o];
#pragma unroll
    for (int d = 0; d < FIN; d++) acc += xs[li][d] * ws[d * DD + o];
    d_x[(size_t)(n0 + li) * DD + o] = fmaxf(acc, 0.0f);
}

// ---------------- [3] prep: B chunk images ----------------
__global__ void k_prep_B(const float* __restrict__ mw2, const float* __restrict__ mb2) {
    int chunk = blockIdx.x;  // 0 .. LL*NCHUNK-1
    int l = chunk / NCHUNK, kc = chunk % NCHUNK;
    const float* sp = (kc < 64) ? (mw2 + ((size_t)l * 64 + kc) * (DD * DD))
                                : (mb2 + (size_t)l * (DD * DD));
    __half* hb = d_Bh + (size_t)chunk * BCH16;
    for (int i = threadIdx.x; i < DD * DD; i += 256) {
        int d = i >> 6, o = i & 63;  // sp[i] = M[kc][d][o]
        hb[o * BSTRIDE + d] = __float2half_rn(sp[i]);
    }
}

// ---------------- [4] all-layer edge hidden + ones rows ----------------
// blocks [0, LL*512): hT[l][k][e] = relu(ea @ W1[l] + b1[l])
// blocks [LL*512, LL*512 + LL*64): ones rows (bias chunk)
__global__ __launch_bounds__(256) void k_edge_h_all(const float* __restrict__ ea,
                                                    const float* __restrict__ mw1,
                                                    const float* __restrict__ mb1) {
    int bid = blockIdx.x;
    int t = threadIdx.x;
    if (bid >= LL * 512) {
        int j = bid - LL * 512;
        int layer = j / 64, blk = j % 64;
        float* p = d_hT + (size_t)layer * NCHUNK * EE + (size_t)64 * EE + blk * 1024;
        ((float4*)p)[t] = make_float4(1.0f, 1.0f, 1.0f, 1.0f);
        return;
    }
    int layer = bid / 512, eb = bid % 512;
    __shared__ float ws[EIN * HE];
    __shared__ float bs[HE];
    const float* w1 = mw1 + (size_t)layer * EIN * HE;
    const float* b1 = mb1 + (size_t)layer * HE;
    for (int i = t; i < EIN * HE; i += 256) ws[i] = w1[i];
    if (t < HE) bs[t] = b1[t];
    __syncthreads();
    int e = eb * 128 + (t & 127);
    int k0 = (t >> 7) * 32;
    float ev[EIN];
    const float4* ep = (const float4*)(ea + (size_t)e * EIN);
#pragma unroll
    for (int i = 0; i < 4; i++) {
        float4 v = ep[i];
        ev[4 * i + 0] = v.x; ev[4 * i + 1] = v.y;
        ev[4 * i + 2] = v.z; ev[4 * i + 3] = v.w;
    }
    float acc[32];
#pragma unroll
    for (int kk = 0; kk < 32; kk++) acc[kk] = bs[k0 + kk];
#pragma unroll
    for (int j = 0; j < EIN; j++) {
        float evj = ev[j];
#pragma unroll
        for (int kk = 0; kk < 32; kk++) acc[kk] += evj * ws[j * HE + k0 + kk];
    }
    float* hTl = d_hT + (size_t)layer * NCHUNK * EE;
#pragma unroll
    for (int kk = 0; kk < 32; kk++)
        hTl[(size_t)(k0 + kk) * EE + e] = fmaxf(acc[kk], 0.0f);
}

// ---------------- edge message GEMM via warp MMA (R11 verbatim + layer slab) ------
__global__ __launch_bounds__(128) void k_edge_msg_hmma(const int* __restrict__ src,
                                                       const int* __restrict__ dst,
                                                       int layer) {
    __shared__ __half Bs[2][BCH16];  // 2 x 9216 B
    __shared__ float hs[2][128];

    int t = threadIdx.x, wid = t >> 5, lid = t & 31;
    int g = lid >> 2, tig = lid & 3;
    int e0 = blockIdx.x * 128;

    // ---- y fragments in registers (constant across chunks) ----
    float yv[4][16];
    int edge_id[4];
#pragma unroll
    for (int mt = 0; mt < 2; mt++)
#pragma unroll
        for (int rr = 0; rr < 2; rr++) {
            int e = e0 + wid * 32 + mt * 16 + g + rr * 8;
            edge_id[mt * 2 + rr] = e;
            const float* xr = d_x + (size_t)src[e] * DD;
#pragma unroll
            for (int w = 0; w < 4; w++) {
                float2 v0 = *(const float2*)(xr + w * 16 + tig * 2);
                float2 v1 = *(const float2*)(xr + w * 16 + 8 + tig * 2);
                yv[mt * 2 + rr][w * 4 + 0] = v0.x;
                yv[mt * 2 + rr][w * 4 + 1] = v0.y;
                yv[mt * 2 + rr][w * 4 + 2] = v1.x;
                yv[mt * 2 + rr][w * 4 + 3] = v1.y;
            }
        }

    float acc[2][8][4];
#pragma unroll
    for (int mt = 0; mt < 2; mt++)
#pragma unroll
        for (int nt = 0; nt < 8; nt++)
#pragma unroll
            for (int q = 0; q < 4; q++) acc[mt][nt][q] = 0.0f;

    const __half* Bh = d_Bh + (size_t)layer * NCHUNK * BCH16;
    const float* hTl = d_hT + (size_t)layer * NCHUNK * EE;

    uint32_t sB0 = smem_u32(&Bs[0][0]);
    uint32_t sB1 = smem_u32(&Bs[1][0]);
    uint32_t sh0 = smem_u32(&hs[0][0]);
    uint32_t sh1 = smem_u32(&hs[1][0]);

    auto issue_chunk = [&](int kc, int st) {
        const char* gB = (const char*)(Bh + (size_t)kc * BCH16);
        uint32_t sB = st ? sB1 : sB0;
        uint32_t sh = st ? sh1 : sh0;
#pragma unroll
        for (int q = 0; q < 4; q++)
            CP_A16(sB + (t + q * 128) * 16, gB + (size_t)(t + q * 128) * 16);
        if (t < 64) CP_A16(sB + (t + 512) * 16, gB + (size_t)(t + 512) * 16);
        CP_A4(sh + t * 4, (const char*)(hTl + (size_t)kc * EE + e0 + t));
    };

    issue_chunk(0, 0);
    CP_COMMIT();

    for (int kc = 0; kc < NCHUNK; kc++) {
        int st = kc & 1;
        __syncthreads();
        if (kc + 1 < NCHUNK) {
            issue_chunk(kc + 1, st ^ 1);
            CP_COMMIT();
            CP_WAIT1();
        } else {
            CP_WAIT0();
        }
        __syncthreads();

        float h0  = hs[st][wid * 32 + g];
        float h0b = hs[st][wid * 32 + g + 8];
        float h1  = hs[st][wid * 32 + 16 + g];
        float h1b = hs[st][wid * 32 + 16 + g + 8];

#pragma unroll
        for (int w = 0; w < 4; w++) {
            uint32_t ah[2][4];
#pragma unroll
            for (int mt = 0; mt < 2; mt++) {
                float ha = mt ? h1 : h0;
                float hb = mt ? h1b : h0b;
                const float* y0 = yv[mt * 2 + 0];  // row g
                const float* y1 = yv[mt * 2 + 1];  // row g+8
                ah[mt][0] = packh2(ha * y0[w * 4 + 0], ha * y0[w * 4 + 1]);
                ah[mt][1] = packh2(hb * y1[w * 4 + 0], hb * y1[w * 4 + 1]);
                ah[mt][2] = packh2(ha * y0[w * 4 + 2], ha * y0[w * 4 + 3]);
                ah[mt][3] = packh2(hb * y1[w * 4 + 2], hb * y1[w * 4 + 3]);
            }
#pragma unroll
            for (int nt = 0; nt < 8; nt++) {
                int boff = (nt * 8 + g) * BSTRIDE + w * 16 + tig * 2;
                uint32_t b0 = *(const uint32_t*)(&Bs[st][0] + boff);
                uint32_t b1 = *(const uint32_t*)(&Bs[st][0] + boff + 8);
#pragma unroll
                for (int mt = 0; mt < 2; mt++)
                    hmma(acc[mt][nt], ah[mt][0], ah[mt][1], ah[mt][2], ah[mt][3], b0, b1);
            }
        }
    }

    // ---- scatter: agg[dst] += msg / deg ----
#pragma unroll
    for (int mt = 0; mt < 2; mt++)
#pragma unroll
        for (int rr = 0; rr < 2; rr++) {
            int e = edge_id[mt * 2 + rr];
            int dn = dst[e];
            float ic = d_invc[dn];
            float* p = d_agg + (size_t)dn * DD + tig * 2;
#pragma unroll
            for (int nt = 0; nt < 8; nt++) {
                atomicAdd(&p[nt * 8 + 0], acc[mt][nt][rr * 2 + 0] * ic);
                atomicAdd(&p[nt * 8 + 1], acc[mt][nt][rr * 2 + 1] * ic);
            }
        }
}

// ---------------- fused root + GraphNorm + residual + agg-zero -------------------
// One block per graph, 256 threads, dynamic smem.
// xc = relu(agg + x @ rootW + b); GraphNorm(xc); x += norm; agg = 0.
#define GN_SMEM (17408 + 34816 + 256 + 256)  // wsT[64][68] + s[128][68] + mean + var
__global__ __launch_bounds__(256) void k_gnorm_fused(const float* __restrict__ rootw,
                                                     const float* __restrict__ convb,
                                                     const float* __restrict__ gw,
                                                     const float* __restrict__ gb,
                                                     const float* __restrict__ gs) {
    extern __shared__ float sm[];
    float* wsT = sm;                 // [64][68] : wsT[o*68+d] = rootw[d*64+o]
    float* s   = wsT + 64 * 68;      // [128][68]
    float* mean = s + 128 * 68;      // [64]
    float* var  = mean + 64;         // [64]

    int g = blockIdx.x, t = threadIdx.x;
    int q = t >> 6, o = t & 63;
    const size_t base = (size_t)g * 128 * DD;

    // load transposed root weights + x tile
    for (int i = t; i < DD * DD; i += 256) {
        int d = i >> 6, oo = i & 63;
        wsT[oo * 68 + d] = rootw[i];
    }
    for (int i = t; i < 128 * DD; i += 256) s[(i >> 6) * 68 + (i & 63)] = d_x[base + i];
    __syncthreads();

    // root GEMM: 32 nodes per thread (n = q + 4*ii), output column o
    float xc[32];
    float bo = convb[o];
    const float4* wr = (const float4*)(wsT + o * 68);
#pragma unroll 4
    for (int ii = 0; ii < 32; ii++) {
        int n = q + ii * 4;
        float acc = bo + d_agg[base + n * DD + o];
        const float4* xr = (const float4*)(s + n * 68);
#pragma unroll
        for (int d4 = 0; d4 < 16; d4++) {
            float4 xv = xr[d4];
            float4 wv = wr[d4];
            acc += xv.x * wv.x + xv.y * wv.y + xv.z * wv.z + xv.w * wv.w;
        }
        xc[ii] = fmaxf(acc, 0.0f);
    }
    __syncthreads();
#pragma unroll
    for (int ii = 0; ii < 32; ii++) s[(q + ii * 4) * 68 + o] = xc[ii];
    __syncthreads();

    if (t < DD) {
        float m = 0.0f;
        for (int n = 0; n < 128; n++) m += s[n * 68 + t];
        mean[t] = gs[t] * (m * (1.0f / 128.0f));  // pre-scaled mean
    }
    __syncthreads();
    for (int i = t; i < 128 * DD; i += 256) {
        int n = i >> 6, d = i & 63;
        s[n * 68 + d] -= mean[d];
    }
    __syncthreads();
    if (t < DD) {
        float v = 0.0f;
        for (int n = 0; n < 128; n++) {
            float sv = s[n * 68 + t];
            v += sv * sv;
        }
        var[t] = v * (1.0f / 128.0f);
    }
    __syncthreads();
    for (int i = t; i < 128 * DD; i += 256) {
        int n = i >> 6, d = i & 63;
        float xn = gw[d] * s[n * 68 + d] * rsqrtf(var[d] + EPSV) + gb[d];
        size_t gi = base + i;
        d_x[gi] = xn + d_x[gi];
        d_agg[gi] = 0.0f;  // ready for next layer
    }
}

// ---------------- Set2Set (3 steps) + head, one block per graph ----------------
__global__ __launch_bounds__(128) void k_s2s(const float* __restrict__ wih,
                                             const float* __restrict__ whh,
                                             const float* __restrict__ bih,
                                             const float* __restrict__ bhh,
                                             const float* __restrict__ hw1,
                                             const float* __restrict__ hb1,
                                             const float* __restrict__ hw2,
                                             const float* __restrict__ hb2,
                                             float* __restrict__ out) {
    __shared__ float sx[128][DD + 1];
    __shared__ float q_star[2 * DD];
    __shared__ float sh[DD], sc[DD];
    __shared__ float gates[4 * DD];
    __shared__ float red[128];
    __shared__ float sa[128];
    __shared__ float sr[DD];
    int g = blockIdx.x, t = threadIdx.x;
    const float* xg = d_x + (size_t)g * 128 * DD;
    for (int i = t; i < 128 * DD; i += 128) sx[i >> 6][i & 63] = xg[i];
    q_star[t] = 0.0f;
    if (t < DD) { sh[t] = 0.0f; sc[t] = 0.0f; }
    __syncthreads();

    for (int step = 0; step < NSTEPS; step++) {
#pragma unroll
        for (int rr = 0; rr < 2; rr++) {
            int r = t + rr * 128;
            float acc = bih[r] + bhh[r];
            const float* wr = wih + (size_t)r * (2 * DD);
            for (int j = 0; j < 2 * DD; j++) acc += q_star[j] * wr[j];
            const float* vr = whh + (size_t)r * DD;
            for (int j = 0; j < DD; j++) acc += sh[j] * vr[j];
            gates[r] = acc;
        }
        __syncthreads();
        if (t < DD) {
            float ig = 1.0f / (1.0f + expf(-gates[t]));
            float fg = 1.0f / (1.0f + expf(-gates[DD + t]));
            float gg = tanhf(gates[2 * DD + t]);
            float og = 1.0f / (1.0f + expf(-gates[3 * DD + t]));
            float c = fg * sc[t] + ig * gg;
            sc[t] = c;
            sh[t] = og * tanhf(c);
        }
        __syncthreads();
        float ee = 0.0f;
#pragma unroll
        for (int d = 0; d < DD; d++) ee += sx[t][d] * sh[d];
        red[t] = ee;
        __syncthreads();
        for (int off = 64; off; off >>= 1) {
            if (t < off) red[t] = fmaxf(red[t], red[t + off]);
            __syncthreads();
        }
        float emax = red[0];
        __syncthreads();
        float ex = expf(ee - emax);
        red[t] = ex;
        __syncthreads();
        for (int off = 64; off; off >>= 1) {
            if (t < off) red[t] += red[t + off];
            __syncthreads();
        }
        float denom = red[0];
        sa[t] = ex / denom;
        __syncthreads();
        if (t < DD) {
            float r = 0.0f;
            for (int n = 0; n < 128; n++) r += sa[n] * sx[n][t];
            sr[t] = r;
        }
        __syncthreads();
        q_star[t] = (t < DD) ? sh[t] : sr[t - DD];
        __syncthreads();
    }
    if (t < DD) {
        float acc = hb1[t];
        for (int j = 0; j < 2 * DD; j++) acc += q_star[j] * hw1[j * DD + t];
        red[t] = fmaxf(acc, 0.0f) * hw2[t];
    }
    __syncthreads();
    if (t < 32) {
        float v = red[t] + red[t + 32];
        for (int off = 16; off; off >>= 1) v += __shfl_down_sync(0xffffffffu, v, off);
        if (t == 0) out[g] = v + hb2[0];
    }
}

// ---------------- launch ----------------
extern "C" void kernel_launch(void* const* d_in, const int* in_sizes, int n_in,
                              void* d_out, int out_size) {
    const float* x     = (const float*)d_in[0];
    const int*   ei    = (const int*)d_in[1];
    const float* ea    = (const float*)d_in[2];
    const float* lin0w = (const float*)d_in[4];
    const float* lin0b = (const float*)d_in[5];
    const float* mw1   = (const float*)d_in[6];
    const float* mb1   = (const float*)d_in[7];
    const float* mw2   = (const float*)d_in[8];
    const float* mb2   = (const float*)d_in[9];
    const float* rootw = (const float*)d_in[10];
    const float* convb = (const float*)d_in[11];
    const float* gnw   = (const float*)d_in[12];
    const float* gnb   = (const float*)d_in[13];
    const float* gns   = (const float*)d_in[14];
    const float* wih   = (const float*)d_in[15];
    const float* whh   = (const float*)d_in[16];
    const float* bih   = (const float*)d_in[17];
    const float* bhh   = (const float*)d_in[18];
    const float* hw1   = (const float*)d_in[19];
    const float* hb1   = (const float*)d_in[20];
    const float* hw2   = (const float*)d_in[21];
    const float* hb2   = (const float*)d_in[22];
    float* out = (float*)d_out;

    const int* src = ei;
    const int* dst = ei + EE;

    static int smem_set = 0;
    if (!smem_set) {
        cudaFuncSetAttribute(k_gnorm_fused, cudaFuncAttributeMaxDynamicSharedMemorySize,
                             GN_SMEM);
        smem_set = 1;
    }

    k_zero0<<<(NN * DD) / 256, 256>>>();                               // [0]
    k_count<<<EE / 256, 256>>>(dst);                                   // [1]
    k_lin0<<<NN / 4, 256>>>(x, lin0w, lin0b);                          // [2] (+invc)
    k_prep_B<<<LL * NCHUNK, 256>>>(mw2, mb2);                          // [3]
    k_edge_h_all<<<LL * 512 + LL * 64, 256>>>(ea, mw1, mb1);           // [4]

    for (int l = 0; l < LL; l++) {
        k_edge_msg_hmma<<<EE / 128, 128>>>(src, dst, l);               // [5],[7],[9]
        k_gnorm_fused<<<GG, 256, GN_SMEM>>>(rootw + (size_t)l * DD * DD,
                                            convb + (size_t)l * DD,
                                            gnw + (size_t)l * DD,
                                            gnb + (size_t)l * DD,
                                            gns + (size_t)l * DD);     // [6],[8],[10]
    }

    k_s2s<<<GG, 128>>>(wih, whh, bih, bhh, hw1, hb1, hw2, hb2, out);   // [11]
}